// round 9
// baseline (speedup 1.0000x reference)
#include <cuda_runtime.h>

#define NT 1096
#define NS 2048
#define NH 16
#define NL (NS*NH)         // 32768 lanes
#define CL 8               // replay chunk length
#define NCHUNK 137         // NT / CL
#define NCKPT 136          // checkpoints (chunks 1..136)

__device__ float4 g_gate[NH];             // {melt, alpha, gax, ch}
__device__ float2 g_ckpt[NCKPT * NL];     // (s, hs) at chunk starts

// ── K0: per-h gate table (removes softmax/MUFU from the wide kernel) ──
__global__ void gates_kernel(const float* __restrict__ w_i, const float* __restrict__ w_o,
                             const float* __restrict__ w_l, const float* __restrict__ w_s) {
    const int h = threadIdx.x;
    if (h >= NH) return;
    const float melt = expf(w_s[h]) + 1.0f;
    const float gi   = 1.0f / (1.0f + expf(-w_i[h]));
    const float gl   = 1.0f / (1.0f + expf(-w_l[h]));
    float wmax = w_o[0];
    #pragma unroll
    for (int i = 1; i < NH; ++i) wmax = fmaxf(wmax, w_o[i]);
    float denom = 0.0f;
    #pragma unroll
    for (int i = 0; i < NH; ++i) denom += expf(w_o[i] - wmax);
    const float a = expf(w_o[h] - wmax) / denom;
    const float alpha = 1.0f - gl;
    g_gate[h] = make_float4(melt, alpha, alpha * gi, a * gl / alpha);
}

// ── K1: lean serial state chain; checkpoint (s,hs) every CL steps ──
__global__ __launch_bounds__(128)
void ckpt_kernel(const float* __restrict__ P, const float* __restrict__ T) {
    const int gid  = blockIdx.x * blockDim.x + threadIdx.x;
    const int site = gid >> 4;
    const int h    = gid & 15;
    const float4 gt = g_gate[h];
    const float melt = gt.x, alpha = gt.y, gax = gt.z;

    float s = 0.0f, hs = 0.0f;
    const float* Pp = P + site;
    const float* Tp = T + site;

    // two 8-slot buffers -> prefetch distance 16 iterations (~covers L2 latency)
    float pb0[CL], tb0[CL], pb1[CL], tb1[CL];
    #pragma unroll
    for (int i = 0; i < CL; ++i) { pb0[i] = Pp[i * NS];        tb0[i] = Tp[i * NS]; }
    #pragma unroll
    for (int i = 0; i < CL; ++i) { pb1[i] = Pp[(CL + i) * NS]; tb1[i] = Tp[(CL + i) * NS]; }

    for (int t0 = 0; t0 < NCKPT * CL; t0 += 2 * CL) {    // 1088 steps, 68 iters
        #pragma unroll
        for (int i = 0; i < CL; ++i) {
            const float Pk = pb0[i], Tk = tb0[i];
            if (t0 + 2 * CL < NCKPT * CL) {
                pb0[i] = Pp[(t0 + 2 * CL + i) * NS];
                tb0[i] = Tp[(t0 + 2 * CL + i) * NS];
            }
            const float m    = fminf(fmaxf(Tk, 0.0f) * melt, s);
            const float pin  = (Tk < 0.0f) ? Pk : 0.0f;
            const float rain = (Tk > 0.0f) ? Pk : 0.0f;
            s  = (s - m) + pin;
            hs = alpha * hs + gax * (rain + m);
        }
        g_ckpt[(t0 >> 3) * NL + gid] = make_float2(s, hs);

        #pragma unroll
        for (int i = 0; i < CL; ++i) {
            const float Pk = pb1[i], Tk = tb1[i];
            if (t0 + 3 * CL < NCKPT * CL) {
                pb1[i] = Pp[(t0 + 3 * CL + i) * NS];
                tb1[i] = Tp[(t0 + 3 * CL + i) * NS];
            }
            const float m    = fminf(fmaxf(Tk, 0.0f) * melt, s);
            const float pin  = (Tk < 0.0f) ? Pk : 0.0f;
            const float rain = (Tk > 0.0f) ? Pk : 0.0f;
            s  = (s - m) + pin;
            hs = alpha * hs + gax * (rain + m);
        }
        g_ckpt[((t0 >> 3) + 1) * NL + gid] = make_float2(s, hs);
    }
}

// ── K2: fully-parallel replay of 8 steps per thread; all outputs ──
__global__ __launch_bounds__(256)
void out_kernel(const float* __restrict__ P, const float* __restrict__ T,
                float* __restrict__ Q, float* __restrict__ H, float* __restrict__ S) {
    const int g    = blockIdx.x * blockDim.x + threadIdx.x;  // c*NL + lane
    const int c    = g >> 15;                                // / NL
    const int lane = g & (NL - 1);
    const int site = lane >> 4;
    const int h    = lane & 15;

    const float4 gt = g_gate[h];
    const float melt = gt.x, alpha = gt.y, gax = gt.z, ch = gt.w;

    float s, hs;
    if (c == 0) { s = 0.0f; hs = 0.0f; }
    else { const float2 ck = g_ckpt[(c - 1) * NL + lane]; s = ck.x; hs = ck.y; }

    const int t0 = c * CL;
    const float* Pp = P + site;
    const float* Tp = T + site;
    float pb[CL], tb[CL];
    #pragma unroll
    for (int i = 0; i < CL; ++i) {
        pb[i] = Pp[(size_t)(t0 + i) * NS];
        tb[i] = Tp[(size_t)(t0 + i) * NS];
    }

    float* Hp = H + lane;
    float* Sp = S + lane;

    float qa[CL];
    #pragma unroll
    for (int i = 0; i < CL; ++i) {
        const float Pk = pb[i], Tk = tb[i];
        const float m    = fminf(fmaxf(Tk, 0.0f) * melt, s);
        const float pin  = (Tk < 0.0f) ? Pk : 0.0f;
        const float rain = (Tk > 0.0f) ? Pk : 0.0f;
        s  = (s - m) + pin;
        hs = alpha * hs + gax * (rain + m);

        const size_t off = (size_t)(t0 + i) * NL;
        Hp[off] = hs;
        Sp[off] = s;
        qa[i] = hs * ch;
    }

    // Value-split reduction: 8 values over 16 lanes, 8 SHFLs (validated R3).
    const bool b3 = (h & 8) != 0;
    const bool b2 = (h & 4) != 0;
    const bool b1 = (h & 2) != 0;
    #pragma unroll
    for (int i = 0; i < 4; ++i) {
        const float send = b3 ? qa[i] : qa[i + 4];
        const float recv = __shfl_xor_sync(0xffffffffu, send, 8);
        const float keep = b3 ? qa[i + 4] : qa[i];
        qa[i] = keep + recv;
    }
    #pragma unroll
    for (int i = 0; i < 2; ++i) {
        const float send = b2 ? qa[i] : qa[i + 2];
        const float recv = __shfl_xor_sync(0xffffffffu, send, 4);
        const float keep = b2 ? qa[i + 2] : qa[i];
        qa[i] = keep + recv;
    }
    {
        const float send = b1 ? qa[0] : qa[1];
        const float recv = __shfl_xor_sync(0xffffffffu, send, 2);
        const float keep = b1 ? qa[1] : qa[0];
        qa[0] = keep + recv;
    }
    qa[0] += __shfl_xor_sync(0xffffffffu, qa[0], 1);

    if ((h & 1) == 0)
        Q[(size_t)(t0 + (h >> 1)) * NS + site] = qa[0];
}

extern "C" void kernel_launch(void* const* d_in, const int* in_sizes, int n_in,
                              void* d_out, int out_size) {
    const float* P   = (const float*)d_in[0];
    const float* T   = (const float*)d_in[1];
    const float* w_i = (const float*)d_in[2];
    const float* w_o = (const float*)d_in[3];
    const float* w_l = (const float*)d_in[4];
    const float* w_s = (const float*)d_in[5];

    float* out = (float*)d_out;
    float* Q = out;                                           // [NT, NS]
    float* H = out + (size_t)NT * NS;                         // [NT, NS, NH]
    float* S = out + (size_t)NT * NS + (size_t)NT * NS * NH;  // [NT, NS, NH]

    gates_kernel<<<1, 32>>>(w_i, w_o, w_l, w_s);
    ckpt_kernel <<<NL / 128, 128>>>(P, T);                    // 256 blocks
    out_kernel  <<<(NCHUNK * NL) / 256, 256>>>(P, T, Q, H, S); // 17536 blocks
}

// round 10
// speedup vs baseline: 1.5446x; 1.5446x over previous
#include <cuda_runtime.h>

#define NT 1096
#define NS 2048
#define NH 16
#define NL (NS*NH)          // 32768 lanes
#define UF 8                // NT = 8 * 137

// Transposed interleaved inputs: PT[site][t] = (P[t][site], T[t][site])  (~18MB)
__device__ float2 g_PT[(size_t)NS * NT];

// ── Transpose P,T -> PT[site][t] via smem tiles (coalesced both sides) ──
#define TDIM 32
__global__ __launch_bounds__(256)
void transpose_kernel(const float* __restrict__ P, const float* __restrict__ T) {
    __shared__ float2 tile[TDIM][TDIM + 1];
    const int s0 = blockIdx.x * TDIM;
    const int t0 = blockIdx.y * TDIM;

    #pragma unroll
    for (int r = threadIdx.y; r < TDIM; r += 8) {
        const int t = t0 + r;
        const int s = s0 + threadIdx.x;
        if (t < NT)
            tile[r][threadIdx.x] = make_float2(P[(size_t)t * NS + s],
                                               T[(size_t)t * NS + s]);
    }
    __syncthreads();
    #pragma unroll
    for (int r = threadIdx.y; r < TDIM; r += 8) {
        const int s = s0 + r;
        const int t = t0 + threadIdx.x;
        if (t < NT)
            g_PT[(size_t)s * NT + t] = tile[threadIdx.x][r];
    }
}

// ── Main: serial scan, vectorized broadcast loads, lean store side ──
__global__ __launch_bounds__(256)
void waternet_kernel(const float* __restrict__ w_i, const float* __restrict__ w_o,
                     const float* __restrict__ w_l, const float* __restrict__ w_s,
                     float* __restrict__ Q, float* __restrict__ H, float* __restrict__ S)
{
    const int gid  = blockIdx.x * blockDim.x + threadIdx.x;   // site*NH + h
    const int site = gid >> 4;
    const int h    = gid & 15;

    // Gates (inline; cheap once per thread)
    const float melt = expf(w_s[h]) + 1.0f;
    const float gi   = 1.0f / (1.0f + expf(-w_i[h]));
    const float gl   = 1.0f / (1.0f + expf(-w_l[h]));
    float wmax = w_o[0];
    #pragma unroll
    for (int i = 1; i < NH; ++i) wmax = fmaxf(wmax, w_o[i]);
    float denom = 0.0f;
    #pragma unroll
    for (int i = 0; i < NH; ++i) denom += expf(w_o[i] - wmax);
    const float a = expf(w_o[h] - wmax) / denom;

    const float alpha = 1.0f - gl;
    const float gax   = alpha * gi;         // hs' = alpha*hs + gax*x
    const float ch    = a * gl / alpha;     // q*a = hs' * ch

    float s  = 0.0f;
    float hs = 0.0f;

    // float4 view: one load = 2 timesteps of (P,T); all 16 h-lanes broadcast.
    const float4* PT4 = (const float4*)(g_PT + (size_t)site * NT);
    float* Hp = H + gid;
    float* Sp = S + gid;

    const bool b3 = (h & 8) != 0;
    const bool b2 = (h & 4) != 0;
    const bool b1 = (h & 2) != 0;
    const bool qlane = (h & 1) == 0;
    const int  qidx  = h >> 1;

    // Double-buffered prefetch: 4 LDG.128 per 8-step group.
    float4 pb[4];
    #pragma unroll
    for (int j = 0; j < 4; ++j) pb[j] = PT4[j];

    for (int t0 = 0; t0 < NT; t0 += UF) {
        float4 pc[4];
        #pragma unroll
        for (int j = 0; j < 4; ++j) pc[j] = pb[j];

        if (t0 + UF < NT) {
            const int base = (t0 + UF) >> 1;
            #pragma unroll
            for (int j = 0; j < 4; ++j) pb[j] = PT4[base + j];
        }

        float qa[UF];
        #pragma unroll
        for (int j = 0; j < 4; ++j) {
            #pragma unroll
            for (int u = 0; u < 2; ++u) {
                const float Pk = u ? pc[j].z : pc[j].x;
                const float Tk = u ? pc[j].w : pc[j].y;

                const float m    = fminf(fmaxf(Tk, 0.0f) * melt, s);
                const float pin  = (Tk < 0.0f) ? Pk : 0.0f;
                const float rain = (Tk > 0.0f) ? Pk : 0.0f;
                s  = (s - m) + pin;
                hs = alpha * hs + gax * (rain + m);

                const int i = j * 2 + u;
                const size_t off = (size_t)(t0 + i) * NL;
                Hp[off] = hs;
                Sp[off] = s;
                qa[i] = hs * ch;
            }
        }

        // Value-split reduction: 8 values over 16 lanes in 8 SHFLs (validated R3).
        #pragma unroll
        for (int i = 0; i < 4; ++i) {
            const float send = b3 ? qa[i] : qa[i + 4];
            const float recv = __shfl_xor_sync(0xffffffffu, send, 8);
            const float keep = b3 ? qa[i + 4] : qa[i];
            qa[i] = keep + recv;
        }
        #pragma unroll
        for (int i = 0; i < 2; ++i) {
            const float send = b2 ? qa[i] : qa[i + 2];
            const float recv = __shfl_xor_sync(0xffffffffu, send, 4);
            const float keep = b2 ? qa[i + 2] : qa[i];
            qa[i] = keep + recv;
        }
        {
            const float send = b1 ? qa[0] : qa[1];
            const float recv = __shfl_xor_sync(0xffffffffu, send, 2);
            const float keep = b1 ? qa[1] : qa[0];
            qa[0] = keep + recv;
        }
        qa[0] += __shfl_xor_sync(0xffffffffu, qa[0], 1);

        if (qlane) Q[(size_t)(t0 + qidx) * NS + site] = qa[0];
    }
}

extern "C" void kernel_launch(void* const* d_in, const int* in_sizes, int n_in,
                              void* d_out, int out_size) {
    const float* P   = (const float*)d_in[0];
    const float* T   = (const float*)d_in[1];
    const float* w_i = (const float*)d_in[2];
    const float* w_o = (const float*)d_in[3];
    const float* w_l = (const float*)d_in[4];
    const float* w_s = (const float*)d_in[5];

    float* out = (float*)d_out;
    float* Q = out;                                           // [NT, NS]
    float* H = out + (size_t)NT * NS;                         // [NT, NS, NH]
    float* S = out + (size_t)NT * NS + (size_t)NT * NS * NH;  // [NT, NS, NH]

    dim3 tgrid(NS / TDIM, (NT + TDIM - 1) / TDIM);            // 64 x 35
    transpose_kernel<<<tgrid, dim3(32, 8)>>>(P, T);

    waternet_kernel<<<NL / 256, 256>>>(w_i, w_o, w_l, w_s, Q, H, S);  // 128 blocks
}

// round 11
// speedup vs baseline: 2.1618x; 1.3996x over previous
#include <cuda_runtime.h>

#define NT 1096
#define NS 2048
#define NH 16
#define NL (NS*NH)
#define UF 8                 // NT = 8 * 137
#define SPB 4                // sites per block (64 threads)
#define RS 1104              // padded smem row stride (floats): covers NT+8 overrun, 16B-aligned

__global__ __launch_bounds__(64)
void waternet_kernel(const float* __restrict__ P, const float* __restrict__ T,
                     const float* __restrict__ w_i, const float* __restrict__ w_o,
                     const float* __restrict__ w_l, const float* __restrict__ w_s,
                     float* __restrict__ Q, float* __restrict__ H, float* __restrict__ S)
{
    __shared__ float sP[SPB * RS];
    __shared__ float sT[SPB * RS];

    const int tid = threadIdx.x;
    const int s0  = blockIdx.x * SPB;

    // ── Fill: stage this block's 4 sites' full P/T series into smem ──
    for (int t = tid; t < NT; t += 64) {
        const float4 vp = *(const float4*)(P + (size_t)t * NS + s0);
        const float4 vt = *(const float4*)(T + (size_t)t * NS + s0);
        sP[0 * RS + t] = vp.x; sP[1 * RS + t] = vp.y;
        sP[2 * RS + t] = vp.z; sP[3 * RS + t] = vp.w;
        sT[0 * RS + t] = vt.x; sT[1 * RS + t] = vt.y;
        sT[2 * RS + t] = vt.z; sT[3 * RS + t] = vt.w;
    }
    __syncthreads();

    const int lsite = tid >> 4;          // 0..3
    const int h     = tid & 15;
    const int site  = s0 + lsite;

    // Gates (once per thread)
    const float melt = expf(w_s[h]) + 1.0f;
    const float gi   = 1.0f / (1.0f + expf(-w_i[h]));
    const float gl   = 1.0f / (1.0f + expf(-w_l[h]));
    float wmax = w_o[0];
    #pragma unroll
    for (int i = 1; i < NH; ++i) wmax = fmaxf(wmax, w_o[i]);
    float denom = 0.0f;
    #pragma unroll
    for (int i = 0; i < NH; ++i) denom += expf(w_o[i] - wmax);
    const float a = expf(w_o[h] - wmax) / denom;

    const float alpha = 1.0f - gl;
    const float gax   = alpha * gi;       // hs' = alpha*hs + gax*x
    const float ch    = a * gl / alpha;   // q*a = hs' * ch

    float s  = 0.0f;
    float hs = 0.0f;

    const float4* myP4 = (const float4*)(sP + lsite * RS);
    const float4* myT4 = (const float4*)(sT + lsite * RS);
    float* Hp = H + ((size_t)site * NH + h);
    float* Sp = S + ((size_t)site * NH + h);

    const bool b3 = (h & 8) != 0;
    const bool b2 = (h & 4) != 0;
    const bool b1 = (h & 2) != 0;
    const bool qlane = (h & 1) == 0;
    const int  qidx  = h >> 1;

    // One-group-ahead register prefetch from smem (branch-free; padding absorbs overrun)
    float4 pb0 = myP4[0], pb1 = myP4[1];
    float4 tb0 = myT4[0], tb1 = myT4[1];

    for (int t0 = 0; t0 < NT; t0 += UF) {
        const float4 pA = pb0, pB = pb1, tA = tb0, tB = tb1;
        const int nb = (t0 + UF) >> 2;
        pb0 = myP4[nb]; pb1 = myP4[nb + 1];
        tb0 = myT4[nb]; tb1 = myT4[nb + 1];

        float qa[UF];
        #pragma unroll
        for (int i = 0; i < UF; ++i) {
            const float Pk = (i < 4) ? ((i == 0) ? pA.x : (i == 1) ? pA.y : (i == 2) ? pA.z : pA.w)
                                     : ((i == 4) ? pB.x : (i == 5) ? pB.y : (i == 6) ? pB.z : pB.w);
            const float Tk = (i < 4) ? ((i == 0) ? tA.x : (i == 1) ? tA.y : (i == 2) ? tA.z : tA.w)
                                     : ((i == 4) ? tB.x : (i == 5) ? tB.y : (i == 6) ? tB.z : tB.w);

            const float m    = fminf(fmaxf(Tk, 0.0f) * melt, s);
            const float pin  = (Tk < 0.0f) ? Pk : 0.0f;
            const float rain = (Tk > 0.0f) ? Pk : 0.0f;
            s  = (s - m) + pin;
            hs = alpha * hs + gax * (rain + m);

            const size_t off = (size_t)(t0 + i) * NL;
            Hp[off] = hs;
            Sp[off] = s;
            qa[i] = hs * ch;
        }

        // Value-split reduction: 8 values over 16 lanes in 8 SHFLs (validated).
        #pragma unroll
        for (int i = 0; i < 4; ++i) {
            const float send = b3 ? qa[i] : qa[i + 4];
            const float recv = __shfl_xor_sync(0xffffffffu, send, 8);
            const float keep = b3 ? qa[i + 4] : qa[i];
            qa[i] = keep + recv;
        }
        #pragma unroll
        for (int i = 0; i < 2; ++i) {
            const float send = b2 ? qa[i] : qa[i + 2];
            const float recv = __shfl_xor_sync(0xffffffffu, send, 4);
            const float keep = b2 ? qa[i + 2] : qa[i];
            qa[i] = keep + recv;
        }
        {
            const float send = b1 ? qa[0] : qa[1];
            const float recv = __shfl_xor_sync(0xffffffffu, send, 2);
            const float keep = b1 ? qa[1] : qa[0];
            qa[0] = keep + recv;
        }
        qa[0] += __shfl_xor_sync(0xffffffffu, qa[0], 1);

        if (qlane) Q[(size_t)(t0 + qidx) * NS + site] = qa[0];
    }
}

extern "C" void kernel_launch(void* const* d_in, const int* in_sizes, int n_in,
                              void* d_out, int out_size) {
    const float* P   = (const float*)d_in[0];
    const float* T   = (const float*)d_in[1];
    const float* w_i = (const float*)d_in[2];
    const float* w_o = (const float*)d_in[3];
    const float* w_l = (const float*)d_in[4];
    const float* w_s = (const float*)d_in[5];

    float* out = (float*)d_out;
    float* Q = out;                                           // [NT, NS]
    float* H = out + (size_t)NT * NS;                         // [NT, NS, NH]
    float* S = out + (size_t)NT * NS + (size_t)NT * NS * NH;  // [NT, NS, NH]

    waternet_kernel<<<NS / SPB, 64>>>(P, T, w_i, w_o, w_l, w_s, Q, H, S);  // 512 blocks
}

// round 14
// speedup vs baseline: 2.6320x; 1.2175x over previous
#include <cuda_runtime.h>

#define NT 1096
#define NS 2048
#define NH 16
#define NL (NS*NH)
#define UF 8                 // NT = 8 * 137
#define SPB 4                // sites per block (64 threads)
#define RS 1104              // padded smem row stride (floats): covers NT+8 overrun, 16B-aligned

__global__ __launch_bounds__(64)
void waternet_kernel(const float* __restrict__ P, const float* __restrict__ T,
                     const float* __restrict__ w_i, const float* __restrict__ w_o,
                     const float* __restrict__ w_l, const float* __restrict__ w_s,
                     float* __restrict__ Q, float* __restrict__ H, float* __restrict__ S)
{
    __shared__ float sP[SPB * RS];
    __shared__ float sT[SPB * RS];

    const int tid = threadIdx.x;
    const int s0  = blockIdx.x * SPB;

    // ── Fill: stage this block's 4 sites' full P/T series into smem ──
    for (int t = tid; t < NT; t += 64) {
        const float4 vp = *(const float4*)(P + (size_t)t * NS + s0);
        const float4 vt = *(const float4*)(T + (size_t)t * NS + s0);
        sP[0 * RS + t] = vp.x; sP[1 * RS + t] = vp.y;
        sP[2 * RS + t] = vp.z; sP[3 * RS + t] = vp.w;
        sT[0 * RS + t] = vt.x; sT[1 * RS + t] = vt.y;
        sT[2 * RS + t] = vt.z; sT[3 * RS + t] = vt.w;
    }
    __syncthreads();

    const int lsite = tid >> 4;          // 0..3
    const int h     = tid & 15;
    const int site  = s0 + lsite;

    // Gates (once per thread)
    const float melt = expf(w_s[h]) + 1.0f;
    const float gi   = 1.0f / (1.0f + expf(-w_i[h]));
    const float gl   = 1.0f / (1.0f + expf(-w_l[h]));
    float wmax = w_o[0];
    #pragma unroll
    for (int i = 1; i < NH; ++i) wmax = fmaxf(wmax, w_o[i]);
    float denom = 0.0f;
    #pragma unroll
    for (int i = 0; i < NH; ++i) denom += expf(w_o[i] - wmax);
    const float a = expf(w_o[h] - wmax) / denom;

    const float alpha = 1.0f - gl;
    const float gax   = alpha * gi;       // hs' = alpha*hs + gax*x
    const float ch    = a * gl / alpha;   // q*a = hs' * ch

    float s  = 0.0f;
    float hs = 0.0f;

    const float4* myP4 = (const float4*)(sP + lsite * RS);
    const float4* myT4 = (const float4*)(sT + lsite * RS);

    // 32-bit element offsets (all outputs < 150MB, fits easily)
    float* Hp = H + (unsigned)(site * NH + h);
    float* Sp = S + (unsigned)(site * NH + h);

    const bool b3 = (h & 8) != 0;
    const bool b2 = (h & 4) != 0;
    const bool b1 = (h & 2) != 0;
    const bool qlane = (h & 1) == 0;
    const int  qidx  = h >> 1;

    // One-group-ahead register prefetch from smem (branch-free; padding absorbs overrun)
    float4 pb0 = myP4[0], pb1 = myP4[1];
    float4 tb0 = myT4[0], tb1 = myT4[1];

    unsigned offHS = 0;                          // (t0+i)*NL, 32-bit
    unsigned offQ  = (unsigned)(qidx * NS + site);

    for (int t0 = 0; t0 < NT; t0 += UF) {
        const float4 pA = pb0, pB = pb1, tA = tb0, tB = tb1;
        const int nb = (t0 + UF) >> 2;
        pb0 = myP4[nb]; pb1 = myP4[nb + 1];
        tb0 = myT4[nb]; tb1 = myT4[nb + 1];

        float qa[UF];
        #pragma unroll
        for (int i = 0; i < UF; ++i) {
            const float Pk = (i < 4) ? ((i == 0) ? pA.x : (i == 1) ? pA.y : (i == 2) ? pA.z : pA.w)
                                     : ((i == 4) ? pB.x : (i == 5) ? pB.y : (i == 6) ? pB.z : pB.w);
            const float Tk = (i < 4) ? ((i == 0) ? tA.x : (i == 1) ? tA.y : (i == 2) ? tA.z : tA.w)
                                     : ((i == 4) ? tB.x : (i == 5) ? tB.y : (i == 6) ? tB.z : tB.w);

            const float m    = fminf(fmaxf(Tk, 0.0f) * melt, s);
            const float pin  = (Tk < 0.0f) ? Pk : 0.0f;
            const float rain = (Tk > 0.0f) ? Pk : 0.0f;
            s  = (s - m) + pin;
            hs = alpha * hs + gax * (rain + m);

            // Streaming stores: write-once data, evict-first in L2.
            __stcs(Hp + offHS, hs);
            __stcs(Sp + offHS, s);
            offHS += NL;
            qa[i] = hs * ch;
        }

        // Value-split reduction: 8 values over 16 lanes in 8 SHFLs (validated).
        #pragma unroll
        for (int i = 0; i < 4; ++i) {
            const float send = b3 ? qa[i] : qa[i + 4];
            const float recv = __shfl_xor_sync(0xffffffffu, send, 8);
            const float keep = b3 ? qa[i + 4] : qa[i];
            qa[i] = keep + recv;
        }
        #pragma unroll
        for (int i = 0; i < 2; ++i) {
            const float send = b2 ? qa[i] : qa[i + 2];
            const float recv = __shfl_xor_sync(0xffffffffu, send, 4);
            const float keep = b2 ? qa[i + 2] : qa[i];
            qa[i] = keep + recv;
        }
        {
            const float send = b1 ? qa[0] : qa[1];
            const float recv = __shfl_xor_sync(0xffffffffu, send, 2);
            const float keep = b1 ? qa[1] : qa[0];
            qa[0] = keep + recv;
        }
        qa[0] += __shfl_xor_sync(0xffffffffu, qa[0], 1);

        if (qlane) __stcs(Q + offQ, qa[0]);
        offQ += (unsigned)(UF * NS);
    }
}

extern "C" void kernel_launch(void* const* d_in, const int* in_sizes, int n_in,
                              void* d_out, int out_size) {
    const float* P   = (const float*)d_in[0];
    const float* T   = (const float*)d_in[1];
    const float* w_i = (const float*)d_in[2];
    const float* w_o = (const float*)d_in[3];
    const float* w_l = (const float*)d_in[4];
    const float* w_s = (const float*)d_in[5];

    float* out = (float*)d_out;
    float* Q = out;                                           // [NT, NS]
    float* H = out + (size_t)NT * NS;                         // [NT, NS, NH]
    float* S = out + (size_t)NT * NS + (size_t)NT * NS * NH;  // [NT, NS, NH]

    waternet_kernel<<<NS / SPB, 64>>>(P, T, w_i, w_o, w_l, w_s, Q, H, S);  // 512 blocks
}